// round 1
// baseline (speedup 1.0000x reference)
#include <cuda_runtime.h>
#include <cstdint>

#define N_NODES 50000
#define F_IN    256
#define F_OUT   64

// Scratch for the projected features XW (12.8 MB) — static device global per the
// no-allocation rules.
__device__ float g_XW[(size_t)N_NODES * F_OUT];

// ---------------------------------------------------------------------------
// Stage 1: XW = X @ W    (50000 x 256) @ (256 x 64) -> (50000 x 64), fp32
// Block tile 64x64, BK=32, 128 threads, 8x4 register micro-tile.
// ---------------------------------------------------------------------------
#define BM 64
#define BN 64
#define BK 32
#define TM 8
#define TN 4

__global__ __launch_bounds__(128) void gemm_kernel(const float* __restrict__ X,
                                                   const float* __restrict__ W) {
    // As transposed [k][m], padded to 65 to kill the 8-way store conflict
    __shared__ float As[BK][BM + 1];
    __shared__ float Bs[BK][BN];

    const int t  = threadIdx.x;
    const int tx = t & 15;   // 16 col-groups * TN=4 -> 64 cols
    const int ty = t >> 4;   //  8 row-groups * TM=8 -> 64 rows
    const int rowBase = blockIdx.x * BM;

    float acc[TM][TN];
#pragma unroll
    for (int i = 0; i < TM; i++)
#pragma unroll
        for (int j = 0; j < TN; j++) acc[i][j] = 0.f;

    for (int k0 = 0; k0 < F_IN; k0 += BK) {
        // Load A tile: 64 rows x 32 k = 512 float4, 4 per thread (coalesced on k)
#pragma unroll
        for (int i = 0; i < 4; i++) {
            int f   = t + i * 128;       // 0..511
            int m   = f >> 3;            // row within tile
            int kk4 = f & 7;             // float4 index along k
            int gr  = rowBase + m;
            if (gr >= N_NODES) gr = N_NODES - 1;   // clamp (last block only)
            float4 v = *(const float4*)(X + (size_t)gr * F_IN + k0 + kk4 * 4);
            As[kk4 * 4 + 0][m] = v.x;
            As[kk4 * 4 + 1][m] = v.y;
            As[kk4 * 4 + 2][m] = v.z;
            As[kk4 * 4 + 3][m] = v.w;
        }
        // Load B tile: 32 k x 64 n = 512 float4, direct layout (coalesced on n)
#pragma unroll
        for (int i = 0; i < 4; i++) {
            int f  = t + i * 128;
            int kk = f >> 4;
            int n4 = f & 15;
            *(float4*)&Bs[kk][n4 * 4] =
                *(const float4*)(W + (size_t)(k0 + kk) * F_OUT + n4 * 4);
        }
        __syncthreads();

#pragma unroll
        for (int k = 0; k < BK; k++) {
            float a[TM], b[TN];
#pragma unroll
            for (int i = 0; i < TM; i++) a[i] = As[k][ty * TM + i];
#pragma unroll
            for (int j = 0; j < TN; j++) b[j] = Bs[k][tx * TN + j];
#pragma unroll
            for (int i = 0; i < TM; i++)
#pragma unroll
                for (int j = 0; j < TN; j++)
                    acc[i][j] = fmaf(a[i], b[j], acc[i][j]);
        }
        __syncthreads();
    }

#pragma unroll
    for (int i = 0; i < TM; i++) {
        int gr = rowBase + ty * TM + i;
        if (gr < N_NODES) {
            float4 v = make_float4(acc[i][0], acc[i][1], acc[i][2], acc[i][3]);
            *(float4*)(g_XW + (size_t)gr * F_OUT + tx * TN) = v;
        }
    }
}

// ---------------------------------------------------------------------------
// Stage 2: out[row] += val * XW[col]  over 800k edges.
// 16 threads per edge, each thread: one float4 gather + one red.global.add.v4.f32
// (vector reduction, no return -> REDG path; 4x fewer L2 atomic ops than scalar).
// XW (12.8 MB) and out (12.8 MB) are both L2-resident.
// ---------------------------------------------------------------------------
__global__ __launch_bounds__(256) void scatter_kernel(const int*   __restrict__ erow,
                                                      const int*   __restrict__ ecol,
                                                      const float* __restrict__ evals,
                                                      float*       __restrict__ out,
                                                      int E) {
    int idx = blockIdx.x * blockDim.x + threadIdx.x;
    int e = idx >> 4;       // edge index
    int l = idx & 15;       // float4 slot within the 64-wide feature row
    if (e >= E) return;

    int   r = erow[e];
    int   c = ecol[e];
    float v = evals[e];

    float4 x = ((const float4*)(g_XW + (size_t)c * F_OUT))[l];
    float* dst = out + (size_t)r * F_OUT + l * 4;

    asm volatile("red.global.add.v4.f32 [%0], {%1, %2, %3, %4};"
                 :: "l"(dst), "f"(v * x.x), "f"(v * x.y), "f"(v * x.z), "f"(v * x.w)
                 : "memory");
}

// ---------------------------------------------------------------------------
// Launch (graph-capturable: memset node + 2 kernel nodes, same stream order)
// ---------------------------------------------------------------------------
extern "C" void kernel_launch(void* const* d_in, const int* in_sizes, int n_in,
                              void* d_out, int out_size) {
    const float* X     = (const float*)d_in[0];
    const float* W     = (const float*)d_in[1];
    const int*   erow  = (const int*)d_in[2];
    const int*   ecol  = (const int*)d_in[3];
    const float* evals = (const float*)d_in[4];
    float*       out   = (float*)d_out;
    const int E = in_sizes[2];

    cudaMemsetAsync(d_out, 0, (size_t)out_size * sizeof(float), 0);

    gemm_kernel<<<(N_NODES + BM - 1) / BM, 128>>>(X, W);

    int total = E * 16;
    scatter_kernel<<<(total + 255) / 256, 256>>>(erow, ecol, evals, out, E);
}